// round 3
// baseline (speedup 1.0000x reference)
#include <cuda_runtime.h>
#include <cstdint>

#define BATCH 2
#define SEQ   2048
#define NHEAD 16
#define HDIM  64
#define EDIM  1024

// Scratch (static device globals: allocation-free per harness rules)
__device__ float g_q[(size_t)BATCH * NHEAD * SEQ * HDIM];
__device__ float g_k[(size_t)BATCH * NHEAD * SEQ * HDIM];
__device__ float g_v[(size_t)BATCH * NHEAD * SEQ * HDIM];   // TRANSPOSED: [b,h,d,s]
__device__ float g_att[(size_t)BATCH * SEQ * EDIM];

__device__ __forceinline__ uint32_t f2tf(float f) {
    uint32_t u;
    asm("cvt.rna.tf32.f32 %0, %1;" : "=r"(u) : "f"(f));
    return u;
}

__device__ __forceinline__ uint32_t smem_u32(const void* p) {
    return (uint32_t)__cvta_generic_to_shared(p);
}

#define CP_A16(dst, src) \
    asm volatile("cp.async.cg.shared.global [%0], [%1], 16;" :: "r"(dst), "l"(src) : "memory")
#define CP_COMMIT() asm volatile("cp.async.commit_group;" ::: "memory")
#define CP_WAIT0()  asm volatile("cp.async.wait_group 0;" ::: "memory")
#define CP_WAIT1()  asm volatile("cp.async.wait_group 1;" ::: "memory")

__device__ __forceinline__ void mma_tf32(float* c, const uint32_t* a, const uint32_t* b) {
    asm volatile(
        "mma.sync.aligned.m16n8k8.row.col.f32.tf32.tf32.f32 "
        "{%0,%1,%2,%3}, {%4,%5,%6,%7}, {%8,%9}, {%0,%1,%2,%3};"
        : "+f"(c[0]), "+f"(c[1]), "+f"(c[2]), "+f"(c[3])
        : "r"(a[0]), "r"(a[1]), "r"(a[2]), "r"(a[3]), "r"(b[0]), "r"(b[1]));
}

// Scatter one QKV output element with bias + head_mask. V goes TRANSPOSED.
__device__ __forceinline__ void store_qkv_elem(int r, int e, float v,
                                               const float* bias, const float* mask) {
    int bb  = r >> 11;            // batch (S=2048)
    int s   = r & (SEQ - 1);
    int h   = e / 192;            // 3*hd = 192 per head
    int rem = e - h * 192;
    int which = rem >> 6;         // 0=q, 1=k, 2=v
    int j   = rem & 63;
    float val = (v + bias[e]) * mask[h];
    size_t bh = (size_t)(bb * NHEAD + h);
    if (which == 0)      g_q[(bh * SEQ + s) * HDIM + j] = val;
    else if (which == 1) g_k[(bh * SEQ + s) * HDIM + j] = val;
    else                 g_v[(bh * HDIM + j) * SEQ + s] = val;   // [b,h,d,s]
}

// ---------------------------------------------------------------------------
// tf32 GEMM: C[M,N] = A[M,K] @ W[N,K]^T, cp.async 2-stage double buffer.
// MODE 0: FC epilogue (out = C + bias), A = g_att
// MODE 1: QKV epilogue (scatter bias+mask), A = param
// BM=BN=128, BK=32; 256 thr; warps 4x2, warp tile 32x64. smem stride 36 (CF).
// ---------------------------------------------------------------------------
template <int MODE>
__global__ __launch_bounds__(256)
void gemm_tf32_kernel(const float* __restrict__ A,
                      const float* __restrict__ W,
                      const float* __restrict__ bias,
                      const float* __restrict__ mask,
                      float* __restrict__ out,
                      int M, int N, int K)
{
    extern __shared__ float smp[];
    const int SA = 128 * 36;
    float* sA = smp;             // [2][128][36]
    float* sB = smp + 2 * SA;    // [2][128][36]
    const uint32_t sAu = smem_u32(sA);
    const uint32_t sBu = smem_u32(sB);

    const int tid  = threadIdx.x;
    const int warp = tid >> 5;
    const int lane = tid & 31;
    const int g    = lane >> 2;
    const int t    = lane & 3;
    const int wm   = warp >> 1;
    const int wn   = warp & 1;
    const int m0   = blockIdx.y * 128;
    const int n0   = blockIdx.x * 128;

    const float* Ap = (MODE == 0) ? (const float*)g_att : A;

    const int lrow = tid >> 3;        // 0..31
    const int lcol = (tid & 7) << 2;  // 0,4,...,28

    const float* agp = Ap + (size_t)(m0 + lrow) * K + lcol;
    const float* bgp = W  + (size_t)(n0 + lrow) * K + lcol;

    auto gissue = [&](int st, int k0) {
        #pragma unroll
        for (int i = 0; i < 4; i++) {
            uint32_t off = (uint32_t)((st * SA + (lrow + i * 32) * 36 + lcol) << 2);
            CP_A16(sAu + off, agp + (size_t)i * 32 * K + k0);
            CP_A16(sBu + off, bgp + (size_t)i * 32 * K + k0);
        }
        CP_COMMIT();
    };

    float acc[2][8][4] = {};

    gissue(0, 0);
    int stage = 0;
    for (int k0 = 0; k0 < K; k0 += 32, stage ^= 1) {
        if (k0 + 32 < K) { gissue(stage ^ 1, k0 + 32); CP_WAIT1(); }
        else             { CP_WAIT0(); }
        __syncthreads();

        const float* cA = sA + stage * SA;
        const float* cB = sB + stage * SA;

        #pragma unroll
        for (int kk = 0; kk < 4; kk++) {
            uint32_t a[2][4];
            uint32_t bb[8][2];
            #pragma unroll
            for (int mi = 0; mi < 2; mi++) {
                int r = wm * 32 + mi * 16 + g;
                a[mi][0] = f2tf(cA[r * 36 + kk * 8 + t]);
                a[mi][1] = f2tf(cA[(r + 8) * 36 + kk * 8 + t]);
                a[mi][2] = f2tf(cA[r * 36 + kk * 8 + t + 4]);
                a[mi][3] = f2tf(cA[(r + 8) * 36 + kk * 8 + t + 4]);
            }
            #pragma unroll
            for (int ni = 0; ni < 8; ni++) {
                int rn = wn * 64 + ni * 8 + g;
                bb[ni][0] = f2tf(cB[rn * 36 + kk * 8 + t]);
                bb[ni][1] = f2tf(cB[rn * 36 + kk * 8 + t + 4]);
            }
            #pragma unroll
            for (int mi = 0; mi < 2; mi++)
                #pragma unroll
                for (int ni = 0; ni < 8; ni++)
                    mma_tf32(acc[mi][ni], a[mi], bb[ni]);
        }
        __syncthreads();
    }

    // Epilogue
    #pragma unroll
    for (int mi = 0; mi < 2; mi++) {
        #pragma unroll
        for (int ni = 0; ni < 8; ni++) {
            int r0 = m0 + wm * 32 + mi * 16 + g;
            int cc = n0 + wn * 64 + ni * 8 + 2 * t;
            if (MODE == 0) {
                float b0 = bias[cc], b1 = bias[cc + 1];
                out[(size_t)r0 * N + cc]           = acc[mi][ni][0] + b0;
                out[(size_t)r0 * N + cc + 1]       = acc[mi][ni][1] + b1;
                out[(size_t)(r0 + 8) * N + cc]     = acc[mi][ni][2] + b0;
                out[(size_t)(r0 + 8) * N + cc + 1] = acc[mi][ni][3] + b1;
            } else {
                store_qkv_elem(r0,     cc,     acc[mi][ni][0], bias, mask);
                store_qkv_elem(r0,     cc + 1, acc[mi][ni][1], bias, mask);
                store_qkv_elem(r0 + 8, cc,     acc[mi][ni][2], bias, mask);
                store_qkv_elem(r0 + 8, cc + 1, acc[mi][ni][3], bias, mask);
            }
        }
    }
}

// ---------------------------------------------------------------------------
// Flash attention: CTA = (b, h, 64-row q-tile), 128 thr.
// cp.async double-buffered K/V, V pre-transposed in gmem.
// smem stride 68 (== 4 mod 32) -> conflict-free fragment reads.
// ---------------------------------------------------------------------------
__global__ __launch_bounds__(128)
void flash_attn_kernel()
{
    extern __shared__ float sm[];
    const int ST = 64 * 68;
    float* sQ = sm;               // also reused as P
    const uint32_t smu = smem_u32(sm);

    const int tid  = threadIdx.x;
    const int warp = tid >> 5;
    const int lane = tid & 31;
    const int g    = lane >> 2;
    const int t    = lane & 3;
    const int qt = blockIdx.x;
    const int h  = blockIdx.y;
    const int b  = blockIdx.z;

    const size_t baseQK = ((size_t)(b * NHEAD + h)) * SEQ * HDIM;
    const float* Qg = g_q + baseQK + (size_t)qt * 64 * HDIM;
    const float* Kg = g_k + baseQK;
    const float* Vg = g_v + ((size_t)(b * NHEAD + h)) * HDIM * SEQ;   // [d][s]

    // --- async load Q tile ---
    #pragma unroll
    for (int i = 0; i < 8; i++) {
        int id = tid + i * 128;
        int r  = id >> 4;
        int c  = (id & 15) << 2;
        CP_A16(smu + ((r * 68 + c) << 2), Qg + r * HDIM + c);
    }
    CP_COMMIT();

    auto load_kv = [&](int st, int kt) {
        #pragma unroll
        for (int i = 0; i < 8; i++) {
            int id = tid + i * 128;
            int r  = id >> 4;
            int c  = (id & 15) << 2;
            CP_A16(smu + (((1 + st) * ST + r * 68 + c) << 2),
                   Kg + ((size_t)kt * 64 + r) * HDIM + c);
            CP_A16(smu + (((3 + st) * ST + r * 68 + c) << 2),
                   Vg + (size_t)r * SEQ + kt * 64 + c);
        }
        CP_COMMIT();
    };

    load_kv(0, 0);
    CP_WAIT1();       // Q group done (KV0 may still be in flight)
    __syncthreads();

    // Extract Q A-fragments once; sQ region then becomes P.
    uint32_t qa[8][4];
    const int pr = warp * 16 + g;
    #pragma unroll
    for (int kk = 0; kk < 8; kk++) {
        qa[kk][0] = f2tf(sQ[pr * 68 + kk * 8 + t]);
        qa[kk][1] = f2tf(sQ[(pr + 8) * 68 + kk * 8 + t]);
        qa[kk][2] = f2tf(sQ[pr * 68 + kk * 8 + t + 4]);
        qa[kk][3] = f2tf(sQ[(pr + 8) * 68 + kk * 8 + t + 4]);
    }

    float oc[8][4] = {};
    float m0 = -1e30f, m1 = -1e30f, l0 = 0.0f, l1 = 0.0f;
    const float LOG2E = 1.4426950408889634f;
    const float SCL   = 0.125f;   // 1/sqrt(64)

    int st = 0;
    for (int kt = 0; kt < SEQ / 64; kt++, st ^= 1) {
        if (kt + 1 < SEQ / 64) { load_kv(st ^ 1, kt + 1); CP_WAIT1(); }
        else                   { CP_WAIT0(); }
        __syncthreads();

        const float* cK = sm + (1 + st) * ST;
        const float* cV = sm + (3 + st) * ST;

        // S = Q @ K^T
        float sc[8][4] = {};
        #pragma unroll
        for (int kk = 0; kk < 8; kk++) {
            #pragma unroll
            for (int ni = 0; ni < 8; ni++) {
                uint32_t bb[2];
                int rn = ni * 8 + g;
                bb[0] = f2tf(cK[rn * 68 + kk * 8 + t]);
                bb[1] = f2tf(cK[rn * 68 + kk * 8 + t + 4]);
                mma_tf32(sc[ni], qa[kk], bb);
            }
        }

        // online softmax (rows pr, pr+8)
        #pragma unroll
        for (int ni = 0; ni < 8; ni++)
            #pragma unroll
            for (int j = 0; j < 4; j++) sc[ni][j] *= SCL;

        float mx0 = -1e30f, mx1 = -1e30f;
        #pragma unroll
        for (int ni = 0; ni < 8; ni++) {
            mx0 = fmaxf(mx0, fmaxf(sc[ni][0], sc[ni][1]));
            mx1 = fmaxf(mx1, fmaxf(sc[ni][2], sc[ni][3]));
        }
        mx0 = fmaxf(mx0, __shfl_xor_sync(0xffffffffu, mx0, 1));
        mx0 = fmaxf(mx0, __shfl_xor_sync(0xffffffffu, mx0, 2));
        mx1 = fmaxf(mx1, __shfl_xor_sync(0xffffffffu, mx1, 1));
        mx1 = fmaxf(mx1, __shfl_xor_sync(0xffffffffu, mx1, 2));

        float mn0 = fmaxf(m0, mx0);
        float mn1 = fmaxf(m1, mx1);
        float a0 = exp2f((m0 - mn0) * LOG2E);
        float a1 = exp2f((m1 - mn1) * LOG2E);
        m0 = mn0; m1 = mn1;

        float rs0 = 0.0f, rs1 = 0.0f;
        #pragma unroll
        for (int ni = 0; ni < 8; ni++) {
            sc[ni][0] = exp2f((sc[ni][0] - m0) * LOG2E);
            sc[ni][1] = exp2f((sc[ni][1] - m0) * LOG2E);
            sc[ni][2] = exp2f((sc[ni][2] - m1) * LOG2E);
            sc[ni][3] = exp2f((sc[ni][3] - m1) * LOG2E);
            rs0 += sc[ni][0] + sc[ni][1];
            rs1 += sc[ni][2] + sc[ni][3];
        }
        rs0 += __shfl_xor_sync(0xffffffffu, rs0, 1);
        rs0 += __shfl_xor_sync(0xffffffffu, rs0, 2);
        rs1 += __shfl_xor_sync(0xffffffffu, rs1, 1);
        rs1 += __shfl_xor_sync(0xffffffffu, rs1, 2);
        l0 = l0 * a0 + rs0;
        l1 = l1 * a1 + rs1;

        #pragma unroll
        for (int ni = 0; ni < 8; ni++) {
            oc[ni][0] *= a0; oc[ni][1] *= a0;
            oc[ni][2] *= a1; oc[ni][3] *= a1;
        }

        // store P (raw fp32; warp-private rows of sQ region)
        #pragma unroll
        for (int ni = 0; ni < 8; ni++) {
            int cc = ni * 8 + 2 * t;
            sQ[pr * 68 + cc]           = sc[ni][0];
            sQ[pr * 68 + cc + 1]       = sc[ni][1];
            sQ[(pr + 8) * 68 + cc]     = sc[ni][2];
            sQ[(pr + 8) * 68 + cc + 1] = sc[ni][3];
        }
        __syncwarp();

        // O += P @ V   (V transposed: cV[d][kpos])
        #pragma unroll
        for (int kk = 0; kk < 8; kk++) {
            uint32_t pa[4];
            pa[0] = f2tf(sQ[pr * 68 + kk * 8 + t]);
            pa[1] = f2tf(sQ[(pr + 8) * 68 + kk * 8 + t]);
            pa[2] = f2tf(sQ[pr * 68 + kk * 8 + t + 4]);
            pa[3] = f2tf(sQ[(pr + 8) * 68 + kk * 8 + t + 4]);
            #pragma unroll
            for (int ni = 0; ni < 8; ni++) {
                uint32_t bb[2];
                int rn = ni * 8 + g;
                bb[0] = f2tf(cV[rn * 68 + kk * 8 + t]);
                bb[1] = f2tf(cV[rn * 68 + kk * 8 + t + 4]);
                mma_tf32(oc[ni], pa, bb);
            }
        }
        __syncthreads();
    }

    // epilogue: normalize, write g_att as [B, S, H*hd]
    float i0 = 1.0f / l0;
    float i1 = 1.0f / l1;
    int r0 = qt * 64 + warp * 16 + g;
    float* Og = g_att + (size_t)b * SEQ * EDIM + (size_t)h * HDIM;
    #pragma unroll
    for (int ni = 0; ni < 8; ni++) {
        int cc = ni * 8 + 2 * t;
        Og[(size_t)r0 * EDIM + cc]           = oc[ni][0] * i0;
        Og[(size_t)r0 * EDIM + cc + 1]       = oc[ni][1] * i0;
        Og[(size_t)(r0 + 8) * EDIM + cc]     = oc[ni][2] * i1;
        Og[(size_t)(r0 + 8) * EDIM + cc + 1] = oc[ni][3] * i1;
    }
}

extern "C" void kernel_launch(void* const* d_in, const int* in_sizes, int n_in,
                              void* d_out, int out_size)
{
    const float* x     = (const float*)d_in[0];
    const float* hmask = (const float*)d_in[1];
    const float* qkv_w = (const float*)d_in[2];
    const float* qkv_b = (const float*)d_in[3];
    const float* fc_w  = (const float*)d_in[4];
    const float* fc_b  = (const float*)d_in[5];
    float* out = (float*)d_out;

    const int gemm_smem = 4 * 128 * 36 * (int)sizeof(float);   // 73728
    const int fa_smem   = 5 * 64 * 68 * (int)sizeof(float);    // 87040

    cudaFuncSetAttribute(gemm_tf32_kernel<1>,
                         cudaFuncAttributeMaxDynamicSharedMemorySize, gemm_smem);
    cudaFuncSetAttribute(gemm_tf32_kernel<0>,
                         cudaFuncAttributeMaxDynamicSharedMemorySize, gemm_smem);
    cudaFuncSetAttribute(flash_attn_kernel,
                         cudaFuncAttributeMaxDynamicSharedMemorySize, fa_smem);

    // 1) QKV projection + bias + head_mask + scatter (V transposed)
    gemm_tf32_kernel<1><<<dim3(3 * EDIM / 128, BATCH * SEQ / 128), 256, gemm_smem>>>(
        x, qkv_w, qkv_b, hmask, nullptr, BATCH * SEQ, 3 * EDIM, EDIM);

    // 2) flash attention -> g_att [B,S,D]
    flash_attn_kernel<<<dim3(SEQ / 64, NHEAD, BATCH), 128, fa_smem>>>();

    // 3) output projection + bias -> d_out
    gemm_tf32_kernel<0><<<dim3(EDIM / 128, BATCH * SEQ / 128), 256, gemm_smem>>>(
        nullptr, fc_w, fc_b, nullptr, out, BATCH * SEQ, EDIM, EDIM);
}

// round 4
// speedup vs baseline: 1.2346x; 1.2346x over previous
#include <cuda_runtime.h>
#include <cstdint>

#define BATCH 2
#define SEQ   2048
#define NHEAD 16
#define HDIM  64
#define EDIM  1024

// Scratch (static device globals: allocation-free per harness rules)
__device__ float g_q[(size_t)BATCH * NHEAD * SEQ * HDIM];     // tf32
__device__ float g_k[(size_t)BATCH * NHEAD * SEQ * HDIM];     // tf32
__device__ float g_v[(size_t)BATCH * NHEAD * SEQ * HDIM];     // tf32, TRANSPOSED [b,h,d,s]
__device__ float g_att[(size_t)BATCH * SEQ * EDIM];           // tf32
__device__ float g_xc[(size_t)BATCH * SEQ * EDIM];            // x as tf32
__device__ float g_wqkv[(size_t)3 * EDIM * EDIM];             // qkv_w as tf32
__device__ float g_wfc[(size_t)EDIM * EDIM];                  // fc_w as tf32

__device__ __forceinline__ uint32_t f2tf(float f) {
    uint32_t u;
    asm("cvt.rna.tf32.f32 %0, %1;" : "=r"(u) : "f"(f));
    return u;
}

__device__ __forceinline__ uint32_t smem_u32(const void* p) {
    return (uint32_t)__cvta_generic_to_shared(p);
}

#define CP_A16(dst, src) \
    asm volatile("cp.async.cg.shared.global [%0], [%1], 16;" :: "r"(dst), "l"(src) : "memory")
#define CP_COMMIT() asm volatile("cp.async.commit_group;" ::: "memory")
#define CP_WAIT0()  asm volatile("cp.async.wait_group 0;" ::: "memory")
#define CP_WAIT1()  asm volatile("cp.async.wait_group 1;" ::: "memory")

__device__ __forceinline__ void mma_tf32(float* c, const uint32_t* a, const uint32_t* b) {
    asm volatile(
        "mma.sync.aligned.m16n8k8.row.col.f32.tf32.tf32.f32 "
        "{%0,%1,%2,%3}, {%4,%5,%6,%7}, {%8,%9}, {%0,%1,%2,%3};"
        : "+f"(c[0]), "+f"(c[1]), "+f"(c[2]), "+f"(c[3])
        : "r"(a[0]), "r"(a[1]), "r"(a[2]), "r"(a[3]), "r"(b[0]), "r"(b[1]));
}

// ---------------------------------------------------------------------------
// Elementwise fp32 -> tf32 conversion (memory-bound, cheap)
// ---------------------------------------------------------------------------
__global__ void cvt_tf32_kernel(const float* __restrict__ in,
                                float* __restrict__ out, int n4)
{
    int i = blockIdx.x * blockDim.x + threadIdx.x;
    if (i >= n4) return;
    float4 v = ((const float4*)in)[i];
    uint4 o;
    o.x = f2tf(v.x); o.y = f2tf(v.y); o.z = f2tf(v.z); o.w = f2tf(v.w);
    ((uint4*)out)[i] = o;
}

// Scatter one QKV output element with bias + head_mask, stored as tf32.
// V goes TRANSPOSED [b,h,d,s].
__device__ __forceinline__ void store_qkv_elem(int r, int e, float v,
                                               const float* bias, const float* mask) {
    int bb  = r >> 11;            // batch (S=2048)
    int s   = r & (SEQ - 1);
    int h   = e / 192;            // 3*hd = 192 per head
    int rem = e - h * 192;
    int which = rem >> 6;         // 0=q, 1=k, 2=v
    int j   = rem & 63;
    float val = __uint_as_float(f2tf((v + bias[e]) * mask[h]));
    size_t bh = (size_t)(bb * NHEAD + h);
    if (which == 0)      g_q[(bh * SEQ + s) * HDIM + j] = val;
    else if (which == 1) g_k[(bh * SEQ + s) * HDIM + j] = val;
    else                 g_v[(bh * HDIM + j) * SEQ + s] = val;
}

// ---------------------------------------------------------------------------
// tf32 GEMM: C[M,N] = A[M,K] @ W[N,K]^T. Inputs ALREADY tf32 in gmem,
// so the hot loop is pure cp.async + LDS + MMA (zero cvt).
// MODE 0: FC epilogue (out = C + bias fp32), A = g_att
// MODE 1: QKV epilogue (scatter bias+mask, tf32), A = g_xc
// BM=BN=128, BK=32; 256 thr; warps 4x2, warp tile 32x64. smem stride 36 (CF).
// ---------------------------------------------------------------------------
template <int MODE>
__global__ __launch_bounds__(256)
void gemm_tf32_kernel(const float* __restrict__ bias,
                      const float* __restrict__ mask,
                      float* __restrict__ out,
                      int M, int N, int K)
{
    extern __shared__ float smp[];
    const int SA = 128 * 36;
    float* sA = smp;             // [2][128][36]
    float* sB = smp + 2 * SA;    // [2][128][36]
    const uint32_t sAu = smem_u32(sA);
    const uint32_t sBu = smem_u32(sB);

    const int tid  = threadIdx.x;
    const int warp = tid >> 5;
    const int lane = tid & 31;
    const int g    = lane >> 2;
    const int t    = lane & 3;
    const int wm   = warp >> 1;
    const int wn   = warp & 1;
    const int m0   = blockIdx.y * 128;
    const int n0   = blockIdx.x * 128;

    const float* Ap = (MODE == 0) ? (const float*)g_att  : (const float*)g_xc;
    const float* Wp = (MODE == 0) ? (const float*)g_wfc  : (const float*)g_wqkv;

    const int lrow = tid >> 3;        // 0..31
    const int lcol = (tid & 7) << 2;  // 0,4,...,28

    const float* agp = Ap + (size_t)(m0 + lrow) * K + lcol;
    const float* bgp = Wp + (size_t)(n0 + lrow) * K + lcol;

    auto gissue = [&](int st, int k0) {
        #pragma unroll
        for (int i = 0; i < 4; i++) {
            uint32_t off = (uint32_t)((st * SA + (lrow + i * 32) * 36 + lcol) << 2);
            CP_A16(sAu + off, agp + (size_t)i * 32 * K + k0);
            CP_A16(sBu + off, bgp + (size_t)i * 32 * K + k0);
        }
        CP_COMMIT();
    };

    float acc[2][8][4] = {};

    gissue(0, 0);
    int stage = 0;
    for (int k0 = 0; k0 < K; k0 += 32, stage ^= 1) {
        if (k0 + 32 < K) { gissue(stage ^ 1, k0 + 32); CP_WAIT1(); }
        else             { CP_WAIT0(); }
        __syncthreads();

        const float* cA = sA + stage * SA;
        const float* cB = sB + stage * SA;

        #pragma unroll
        for (int kk = 0; kk < 4; kk++) {
            uint32_t a[2][4];
            uint32_t bb[8][2];
            #pragma unroll
            for (int mi = 0; mi < 2; mi++) {
                int r = wm * 32 + mi * 16 + g;
                a[mi][0] = __float_as_uint(cA[r * 36 + kk * 8 + t]);
                a[mi][1] = __float_as_uint(cA[(r + 8) * 36 + kk * 8 + t]);
                a[mi][2] = __float_as_uint(cA[r * 36 + kk * 8 + t + 4]);
                a[mi][3] = __float_as_uint(cA[(r + 8) * 36 + kk * 8 + t + 4]);
            }
            #pragma unroll
            for (int ni = 0; ni < 8; ni++) {
                int rn = wn * 64 + ni * 8 + g;
                bb[ni][0] = __float_as_uint(cB[rn * 36 + kk * 8 + t]);
                bb[ni][1] = __float_as_uint(cB[rn * 36 + kk * 8 + t + 4]);
            }
            #pragma unroll
            for (int mi = 0; mi < 2; mi++)
                #pragma unroll
                for (int ni = 0; ni < 8; ni++)
                    mma_tf32(acc[mi][ni], a[mi], bb[ni]);
        }
        __syncthreads();
    }

    // Epilogue
    #pragma unroll
    for (int mi = 0; mi < 2; mi++) {
        #pragma unroll
        for (int ni = 0; ni < 8; ni++) {
            int r0 = m0 + wm * 32 + mi * 16 + g;
            int cc = n0 + wn * 64 + ni * 8 + 2 * t;
            if (MODE == 0) {
                float b0 = bias[cc], b1 = bias[cc + 1];
                out[(size_t)r0 * N + cc]           = acc[mi][ni][0] + b0;
                out[(size_t)r0 * N + cc + 1]       = acc[mi][ni][1] + b1;
                out[(size_t)(r0 + 8) * N + cc]     = acc[mi][ni][2] + b0;
                out[(size_t)(r0 + 8) * N + cc + 1] = acc[mi][ni][3] + b1;
            } else {
                store_qkv_elem(r0,     cc,     acc[mi][ni][0], bias, mask);
                store_qkv_elem(r0,     cc + 1, acc[mi][ni][1], bias, mask);
                store_qkv_elem(r0 + 8, cc,     acc[mi][ni][2], bias, mask);
                store_qkv_elem(r0 + 8, cc + 1, acc[mi][ni][3], bias, mask);
            }
        }
    }
}

// ---------------------------------------------------------------------------
// Flash attention: CTA = (b, h, 128-row q-tile), 256 thr (8 warps x 16 rows).
// Q/K/V already tf32 in gmem -> pure LDS+MMA inner loops (cvt only for P).
// cp.async double-buffered K/V, V pre-transposed. smem stride 68 (CF banks).
// ---------------------------------------------------------------------------
__global__ __launch_bounds__(256, 2)
void flash_attn_kernel()
{
    extern __shared__ float sm[];
    const int QT = 128 * 68;      // Q region (reused as P)
    const int ST = 64 * 68;       // one K or V stage
    float* sQ = sm;
    const uint32_t smu = smem_u32(sm);

    const int tid  = threadIdx.x;
    const int warp = tid >> 5;
    const int lane = tid & 31;
    const int g    = lane >> 2;
    const int t    = lane & 3;
    const int qt = blockIdx.x;
    const int h  = blockIdx.y;
    const int b  = blockIdx.z;

    const size_t baseQK = ((size_t)(b * NHEAD + h)) * SEQ * HDIM;
    const float* Qg = g_q + baseQK + (size_t)qt * 128 * HDIM;
    const float* Kg = g_k + baseQK;
    const float* Vg = g_v + ((size_t)(b * NHEAD + h)) * HDIM * SEQ;   // [d][s]

    // --- async load Q tile (128x64) ---
    #pragma unroll
    for (int i = 0; i < 8; i++) {
        int id = tid + i * 256;
        int r  = id >> 4;
        int c  = (id & 15) << 2;
        CP_A16(smu + ((r * 68 + c) << 2), Qg + r * HDIM + c);
    }
    CP_COMMIT();

    auto load_kv = [&](int st, int kt) {
        #pragma unroll
        for (int i = 0; i < 4; i++) {
            int id = tid + i * 256;
            int r  = id >> 4;
            int c  = (id & 15) << 2;
            CP_A16(smu + ((QT + st * ST + r * 68 + c) << 2),
                   Kg + ((size_t)kt * 64 + r) * HDIM + c);
            CP_A16(smu + ((QT + 2 * ST + st * ST + r * 68 + c) << 2),
                   Vg + (size_t)r * SEQ + kt * 64 + c);
        }
        CP_COMMIT();
    };

    load_kv(0, 0);
    CP_WAIT1();       // Q group done (KV0 may still be in flight)
    __syncthreads();

    // Extract Q A-fragments once; sQ region then becomes P.
    uint32_t qa[8][4];
    const int pr = warp * 16 + g;
    #pragma unroll
    for (int kk = 0; kk < 8; kk++) {
        qa[kk][0] = __float_as_uint(sQ[pr * 68 + kk * 8 + t]);
        qa[kk][1] = __float_as_uint(sQ[(pr + 8) * 68 + kk * 8 + t]);
        qa[kk][2] = __float_as_uint(sQ[pr * 68 + kk * 8 + t + 4]);
        qa[kk][3] = __float_as_uint(sQ[(pr + 8) * 68 + kk * 8 + t + 4]);
    }
    __syncthreads();   // everyone has their Q frags before sQ is reused as P

    float oc[8][4] = {};
    float m0 = -1e30f, m1 = -1e30f, l0 = 0.0f, l1 = 0.0f;
    const float LOG2E = 1.4426950408889634f;
    const float SCL   = 0.125f;   // 1/sqrt(64)

    int st = 0;
    for (int kt = 0; kt < SEQ / 64; kt++, st ^= 1) {
        if (kt + 1 < SEQ / 64) { load_kv(st ^ 1, kt + 1); CP_WAIT1(); }
        else                   { CP_WAIT0(); }
        __syncthreads();

        const float* cK = sm + QT + st * ST;
        const float* cV = sm + QT + 2 * ST + st * ST;

        // S = Q @ K^T   (this warp: its 16 rows x all 64 cols)
        float sc[8][4] = {};
        #pragma unroll
        for (int kk = 0; kk < 8; kk++) {
            #pragma unroll
            for (int ni = 0; ni < 8; ni++) {
                uint32_t bb[2];
                int rn = ni * 8 + g;
                bb[0] = __float_as_uint(cK[rn * 68 + kk * 8 + t]);
                bb[1] = __float_as_uint(cK[rn * 68 + kk * 8 + t + 4]);
                mma_tf32(sc[ni], qa[kk], bb);
            }
        }

        // online softmax (rows pr, pr+8)
        #pragma unroll
        for (int ni = 0; ni < 8; ni++)
            #pragma unroll
            for (int j = 0; j < 4; j++) sc[ni][j] *= SCL;

        float mx0 = -1e30f, mx1 = -1e30f;
        #pragma unroll
        for (int ni = 0; ni < 8; ni++) {
            mx0 = fmaxf(mx0, fmaxf(sc[ni][0], sc[ni][1]));
            mx1 = fmaxf(mx1, fmaxf(sc[ni][2], sc[ni][3]));
        }
        mx0 = fmaxf(mx0, __shfl_xor_sync(0xffffffffu, mx0, 1));
        mx0 = fmaxf(mx0, __shfl_xor_sync(0xffffffffu, mx0, 2));
        mx1 = fmaxf(mx1, __shfl_xor_sync(0xffffffffu, mx1, 1));
        mx1 = fmaxf(mx1, __shfl_xor_sync(0xffffffffu, mx1, 2));

        float mn0 = fmaxf(m0, mx0);
        float mn1 = fmaxf(m1, mx1);
        float a0 = exp2f((m0 - mn0) * LOG2E);
        float a1 = exp2f((m1 - mn1) * LOG2E);
        m0 = mn0; m1 = mn1;

        float rs0 = 0.0f, rs1 = 0.0f;
        #pragma unroll
        for (int ni = 0; ni < 8; ni++) {
            sc[ni][0] = exp2f((sc[ni][0] - m0) * LOG2E);
            sc[ni][1] = exp2f((sc[ni][1] - m0) * LOG2E);
            sc[ni][2] = exp2f((sc[ni][2] - m1) * LOG2E);
            sc[ni][3] = exp2f((sc[ni][3] - m1) * LOG2E);
            rs0 += sc[ni][0] + sc[ni][1];
            rs1 += sc[ni][2] + sc[ni][3];
        }
        rs0 += __shfl_xor_sync(0xffffffffu, rs0, 1);
        rs0 += __shfl_xor_sync(0xffffffffu, rs0, 2);
        rs1 += __shfl_xor_sync(0xffffffffu, rs1, 1);
        rs1 += __shfl_xor_sync(0xffffffffu, rs1, 2);
        l0 = l0 * a0 + rs0;
        l1 = l1 * a1 + rs1;

        #pragma unroll
        for (int ni = 0; ni < 8; ni++) {
            oc[ni][0] *= a0; oc[ni][1] *= a0;
            oc[ni][2] *= a1; oc[ni][3] *= a1;
        }

        // store P as tf32 (warp-private rows of sQ region)
        #pragma unroll
        for (int ni = 0; ni < 8; ni++) {
            int cc = ni * 8 + 2 * t;
            sQ[pr * 68 + cc]           = __uint_as_float(f2tf(sc[ni][0]));
            sQ[pr * 68 + cc + 1]       = __uint_as_float(f2tf(sc[ni][1]));
            sQ[(pr + 8) * 68 + cc]     = __uint_as_float(f2tf(sc[ni][2]));
            sQ[(pr + 8) * 68 + cc + 1] = __uint_as_float(f2tf(sc[ni][3]));
        }
        __syncwarp();

        // O += P @ V   (V transposed: cV[d][kpos])
        #pragma unroll
        for (int kk = 0; kk < 8; kk++) {
            uint32_t pa[4];
            pa[0] = __float_as_uint(sQ[pr * 68 + kk * 8 + t]);
            pa[1] = __float_as_uint(sQ[(pr + 8) * 68 + kk * 8 + t]);
            pa[2] = __float_as_uint(sQ[pr * 68 + kk * 8 + t + 4]);
            pa[3] = __float_as_uint(sQ[(pr + 8) * 68 + kk * 8 + t + 4]);
            #pragma unroll
            for (int ni = 0; ni < 8; ni++) {
                uint32_t bb[2];
                int rn = ni * 8 + g;
                bb[0] = __float_as_uint(cV[rn * 68 + kk * 8 + t]);
                bb[1] = __float_as_uint(cV[rn * 68 + kk * 8 + t + 4]);
                mma_tf32(oc[ni], pa, bb);
            }
        }
        __syncthreads();
    }

    // epilogue: normalize, write g_att (tf32) as [B, S, H*hd]
    float i0 = 1.0f / l0;
    float i1 = 1.0f / l1;
    int r0 = qt * 128 + warp * 16 + g;
    float* Og = g_att + (size_t)b * SEQ * EDIM + (size_t)h * HDIM;
    #pragma unroll
    for (int ni = 0; ni < 8; ni++) {
        int cc = ni * 8 + 2 * t;
        Og[(size_t)r0 * EDIM + cc]           = __uint_as_float(f2tf(oc[ni][0] * i0));
        Og[(size_t)r0 * EDIM + cc + 1]       = __uint_as_float(f2tf(oc[ni][1] * i0));
        Og[(size_t)(r0 + 8) * EDIM + cc]     = __uint_as_float(f2tf(oc[ni][2] * i1));
        Og[(size_t)(r0 + 8) * EDIM + cc + 1] = __uint_as_float(f2tf(oc[ni][3] * i1));
    }
}

extern "C" void kernel_launch(void* const* d_in, const int* in_sizes, int n_in,
                              void* d_out, int out_size)
{
    const float* x     = (const float*)d_in[0];
    const float* hmask = (const float*)d_in[1];
    const float* qkv_w = (const float*)d_in[2];
    const float* qkv_b = (const float*)d_in[3];
    const float* fc_w  = (const float*)d_in[4];
    const float* fc_b  = (const float*)d_in[5];
    float* out = (float*)d_out;

    const int gemm_smem = 4 * 128 * 36 * (int)sizeof(float);            // 73728
    const int fa_smem   = (128 * 68 + 4 * 64 * 68) * (int)sizeof(float); // 104448

    cudaFuncSetAttribute(gemm_tf32_kernel<1>,
                         cudaFuncAttributeMaxDynamicSharedMemorySize, gemm_smem);
    cudaFuncSetAttribute(gemm_tf32_kernel<0>,
                         cudaFuncAttributeMaxDynamicSharedMemorySize, gemm_smem);
    cudaFuncSetAttribute(flash_attn_kernel,
                         cudaFuncAttributeMaxDynamicSharedMemorySize, fa_smem);

    float* xc   = nullptr; cudaGetSymbolAddress((void**)&xc,   g_xc);
    float* wqkv = nullptr; cudaGetSymbolAddress((void**)&wqkv, g_wqkv);
    float* wfc  = nullptr; cudaGetSymbolAddress((void**)&wfc,  g_wfc);

    // 0) pre-convert operands to tf32 (memory-bound, ~25 us total)
    cvt_tf32_kernel<<<(BATCH * SEQ * EDIM / 4 + 255) / 256, 256>>>(x, xc, BATCH * SEQ * EDIM / 4);
    cvt_tf32_kernel<<<(3 * EDIM * EDIM / 4 + 255) / 256, 256>>>(qkv_w, wqkv, 3 * EDIM * EDIM / 4);
    cvt_tf32_kernel<<<(EDIM * EDIM / 4 + 255) / 256, 256>>>(fc_w, wfc, EDIM * EDIM / 4);

    // 1) QKV projection + bias + head_mask + scatter (q/k tf32, v tf32 transposed)
    gemm_tf32_kernel<1><<<dim3(3 * EDIM / 128, BATCH * SEQ / 128), 256, gemm_smem>>>(
        qkv_b, hmask, nullptr, BATCH * SEQ, 3 * EDIM, EDIM);

    // 2) flash attention -> g_att [B,S,D] (tf32)
    flash_attn_kernel<<<dim3(SEQ / 128, NHEAD, BATCH), 256, fa_smem>>>();

    // 3) output projection + bias -> d_out (fp32)
    gemm_tf32_kernel<0><<<dim3(EDIM / 128, BATCH * SEQ / 128), 256, gemm_smem>>>(
        fc_b, nullptr, out, BATCH * SEQ, EDIM, EDIM);
}

// round 5
// speedup vs baseline: 1.3196x; 1.0688x over previous
#include <cuda_runtime.h>
#include <cstdint>

#define BATCH 2
#define SEQ   2048
#define NHEAD 16
#define HDIM  64
#define EDIM  1024

// Scratch (static device globals: allocation-free per harness rules)
__device__ float g_q[(size_t)BATCH * NHEAD * SEQ * HDIM];     // tf32
__device__ float g_k[(size_t)BATCH * NHEAD * SEQ * HDIM];     // tf32
__device__ float g_v[(size_t)BATCH * NHEAD * SEQ * HDIM];     // tf32, TRANSPOSED [b,h,d,s]
__device__ float g_att[(size_t)BATCH * SEQ * EDIM];           // tf32
__device__ float g_xc[(size_t)BATCH * SEQ * EDIM];            // x as tf32
__device__ float g_wqkv[(size_t)3 * EDIM * EDIM];             // qkv_w as tf32
__device__ float g_wfc[(size_t)EDIM * EDIM];                  // fc_w as tf32

__device__ __forceinline__ uint32_t f2tf(float f) {
    uint32_t u;
    asm("cvt.rna.tf32.f32 %0, %1;" : "=r"(u) : "f"(f));
    return u;
}

__device__ __forceinline__ uint32_t smem_u32(const void* p) {
    return (uint32_t)__cvta_generic_to_shared(p);
}

#define CP_A16(dst, src) \
    asm volatile("cp.async.cg.shared.global [%0], [%1], 16;" :: "r"(dst), "l"(src) : "memory")
#define CP_COMMIT() asm volatile("cp.async.commit_group;" ::: "memory")
#define CP_WAIT0()  asm volatile("cp.async.wait_group 0;" ::: "memory")
#define CP_WAIT1()  asm volatile("cp.async.wait_group 1;" ::: "memory")

__device__ __forceinline__ void mma_tf32(float* c, const uint32_t* a, const uint32_t* b) {
    asm volatile(
        "mma.sync.aligned.m16n8k8.row.col.f32.tf32.tf32.f32 "
        "{%0,%1,%2,%3}, {%4,%5,%6,%7}, {%8,%9}, {%0,%1,%2,%3};"
        : "+f"(c[0]), "+f"(c[1]), "+f"(c[2]), "+f"(c[3])
        : "r"(a[0]), "r"(a[1]), "r"(a[2]), "r"(a[3]), "r"(b[0]), "r"(b[1]));
}

// ---------------------------------------------------------------------------
// Elementwise fp32 -> tf32 conversion (memory-bound, cheap)
// ---------------------------------------------------------------------------
__global__ void cvt_tf32_kernel(const float* __restrict__ in,
                                float* __restrict__ out, int n4)
{
    int i = blockIdx.x * blockDim.x + threadIdx.x;
    if (i >= n4) return;
    float4 v = ((const float4*)in)[i];
    uint4 o;
    o.x = f2tf(v.x); o.y = f2tf(v.y); o.z = f2tf(v.z); o.w = f2tf(v.w);
    ((uint4*)out)[i] = o;
}

// Scatter one QKV output element with bias + head_mask, stored as tf32.
// V goes TRANSPOSED [b,h,d,s].
__device__ __forceinline__ void store_qkv_elem(int r, int e, float v,
                                               const float* bias, const float* mask) {
    int bb  = r >> 11;            // batch (S=2048)
    int s   = r & (SEQ - 1);
    int h   = e / 192;            // 3*hd = 192 per head
    int rem = e - h * 192;
    int which = rem >> 6;         // 0=q, 1=k, 2=v
    int j   = rem & 63;
    float val = __uint_as_float(f2tf((v + bias[e]) * mask[h]));
    size_t bh = (size_t)(bb * NHEAD + h);
    if (which == 0)      g_q[(bh * SEQ + s) * HDIM + j] = val;
    else if (which == 1) g_k[(bh * SEQ + s) * HDIM + j] = val;
    else                 g_v[(bh * HDIM + j) * SEQ + s] = val;
}

// ---------------------------------------------------------------------------
// tf32 GEMM: C[M,N] = A[M,K] @ W[N,K]^T. Inputs already tf32 in gmem.
// 3-stage cp.async pipeline, ONE __syncthreads per K-step.
// MODE 0: FC epilogue (out = C + bias fp32), A = g_att
// MODE 1: QKV epilogue (scatter bias+mask, tf32), A = g_xc
// BM=BN=128, BK=32; 256 thr (4x2 warps, 32x64 warp tile); stride 36 (CF).
// ---------------------------------------------------------------------------
template <int MODE>
__global__ __launch_bounds__(256, 2)
void gemm_tf32_kernel(const float* __restrict__ bias,
                      const float* __restrict__ mask,
                      float* __restrict__ out,
                      int M, int N, int K)
{
    extern __shared__ float smp[];
    const int SA = 128 * 36;               // one operand tile
    const uint32_t smu = smem_u32(smp);

    const int tid  = threadIdx.x;
    const int warp = tid >> 5;
    const int lane = tid & 31;
    const int g    = lane >> 2;
    const int t    = lane & 3;
    const int wm   = warp >> 1;
    const int wn   = warp & 1;
    const int m0   = blockIdx.y * 128;
    const int n0   = blockIdx.x * 128;

    const float* Ap = (MODE == 0) ? (const float*)g_att : (const float*)g_xc;
    const float* Wp = (MODE == 0) ? (const float*)g_wfc : (const float*)g_wqkv;

    const int lrow = tid >> 3;        // 0..31
    const int lcol = (tid & 7) << 2;  // 0,4,...,28

    const float* agp = Ap + (size_t)(m0 + lrow) * K + lcol;
    const float* bgp = Wp + (size_t)(n0 + lrow) * K + lcol;

    auto gissue = [&](int st, int k0) {
        #pragma unroll
        for (int i = 0; i < 4; i++) {
            uint32_t offA = (uint32_t)((st * 2 * SA + (lrow + i * 32) * 36 + lcol) << 2);
            CP_A16(smu + offA,                 agp + (size_t)i * 32 * K + k0);
            CP_A16(smu + offA + (SA << 2),     bgp + (size_t)i * 32 * K + k0);
        }
        CP_COMMIT();
    };

    float acc[2][8][4] = {};

    const int NK = K / 32;
    gissue(0, 0);
    gissue(1, 32);

    for (int ki = 0; ki < NK; ki++) {
        if (ki + 2 < NK) { CP_WAIT1(); }
        else             { CP_WAIT0(); }
        __syncthreads();
        // slot (ki+2)%3 == slot (ki-1)%3: all warps finished reading it
        if (ki + 2 < NK) gissue((ki + 2) % 3, (ki + 2) * 32);

        const float* cA = smp + (ki % 3) * 2 * SA;
        const float* cB = cA + SA;

        #pragma unroll
        for (int kk = 0; kk < 4; kk++) {
            uint32_t a[2][4];
            uint32_t bb[8][2];
            #pragma unroll
            for (int mi = 0; mi < 2; mi++) {
                int r = wm * 32 + mi * 16 + g;
                a[mi][0] = __float_as_uint(cA[r * 36 + kk * 8 + t]);
                a[mi][1] = __float_as_uint(cA[(r + 8) * 36 + kk * 8 + t]);
                a[mi][2] = __float_as_uint(cA[r * 36 + kk * 8 + t + 4]);
                a[mi][3] = __float_as_uint(cA[(r + 8) * 36 + kk * 8 + t + 4]);
            }
            #pragma unroll
            for (int ni = 0; ni < 8; ni++) {
                int rn = wn * 64 + ni * 8 + g;
                bb[ni][0] = __float_as_uint(cB[rn * 36 + kk * 8 + t]);
                bb[ni][1] = __float_as_uint(cB[rn * 36 + kk * 8 + t + 4]);
            }
            #pragma unroll
            for (int mi = 0; mi < 2; mi++)
                #pragma unroll
                for (int ni = 0; ni < 8; ni++)
                    mma_tf32(acc[mi][ni], a[mi], bb[ni]);
        }
    }

    // Epilogue
    #pragma unroll
    for (int mi = 0; mi < 2; mi++) {
        #pragma unroll
        for (int ni = 0; ni < 8; ni++) {
            int r0 = m0 + wm * 32 + mi * 16 + g;
            int cc = n0 + wn * 64 + ni * 8 + 2 * t;
            if (MODE == 0) {
                float b0 = bias[cc], b1 = bias[cc + 1];
                out[(size_t)r0 * N + cc]           = acc[mi][ni][0] + b0;
                out[(size_t)r0 * N + cc + 1]       = acc[mi][ni][1] + b1;
                out[(size_t)(r0 + 8) * N + cc]     = acc[mi][ni][2] + b0;
                out[(size_t)(r0 + 8) * N + cc + 1] = acc[mi][ni][3] + b1;
            } else {
                store_qkv_elem(r0,     cc,     acc[mi][ni][0], bias, mask);
                store_qkv_elem(r0,     cc + 1, acc[mi][ni][1], bias, mask);
                store_qkv_elem(r0 + 8, cc,     acc[mi][ni][2], bias, mask);
                store_qkv_elem(r0 + 8, cc + 1, acc[mi][ni][3], bias, mask);
            }
        }
    }
}

// ---------------------------------------------------------------------------
// Flash attention: CTA = (b, h, 128-row q-tile), 256 thr (8 warps x 16 rows).
// Q/K/V already tf32 in gmem -> pure LDS+MMA inner loops (cvt only for P).
// cp.async double-buffered K/V, V pre-transposed. smem stride 68 (CF banks).
// ---------------------------------------------------------------------------
__global__ __launch_bounds__(256, 2)
void flash_attn_kernel()
{
    extern __shared__ float sm[];
    const int QT = 128 * 68;      // Q region (reused as P)
    const int ST = 64 * 68;       // one K or V stage
    float* sQ = sm;
    const uint32_t smu = smem_u32(sm);

    const int tid  = threadIdx.x;
    const int warp = tid >> 5;
    const int lane = tid & 31;
    const int g    = lane >> 2;
    const int t    = lane & 3;
    const int qt = blockIdx.x;
    const int h  = blockIdx.y;
    const int b  = blockIdx.z;

    const size_t baseQK = ((size_t)(b * NHEAD + h)) * SEQ * HDIM;
    const float* Qg = g_q + baseQK + (size_t)qt * 128 * HDIM;
    const float* Kg = g_k + baseQK;
    const float* Vg = g_v + ((size_t)(b * NHEAD + h)) * HDIM * SEQ;   // [d][s]

    // --- async load Q tile (128x64) ---
    #pragma unroll
    for (int i = 0; i < 8; i++) {
        int id = tid + i * 256;
        int r  = id >> 4;
        int c  = (id & 15) << 2;
        CP_A16(smu + ((r * 68 + c) << 2), Qg + r * HDIM + c);
    }
    CP_COMMIT();

    auto load_kv = [&](int st, int kt) {
        #pragma unroll
        for (int i = 0; i < 4; i++) {
            int id = tid + i * 256;
            int r  = id >> 4;
            int c  = (id & 15) << 2;
            CP_A16(smu + ((QT + st * ST + r * 68 + c) << 2),
                   Kg + ((size_t)kt * 64 + r) * HDIM + c);
            CP_A16(smu + ((QT + 2 * ST + st * ST + r * 68 + c) << 2),
                   Vg + (size_t)r * SEQ + kt * 64 + c);
        }
        CP_COMMIT();
    };

    load_kv(0, 0);
    CP_WAIT1();       // Q group done (KV0 may still be in flight)
    __syncthreads();

    // Extract Q A-fragments once; sQ region then becomes P.
    uint32_t qa[8][4];
    const int pr = warp * 16 + g;
    #pragma unroll
    for (int kk = 0; kk < 8; kk++) {
        qa[kk][0] = __float_as_uint(sQ[pr * 68 + kk * 8 + t]);
        qa[kk][1] = __float_as_uint(sQ[(pr + 8) * 68 + kk * 8 + t]);
        qa[kk][2] = __float_as_uint(sQ[pr * 68 + kk * 8 + t + 4]);
        qa[kk][3] = __float_as_uint(sQ[(pr + 8) * 68 + kk * 8 + t + 4]);
    }
    __syncthreads();   // everyone has their Q frags before sQ is reused as P

    float oc[8][4] = {};
    float m0 = -1e30f, m1 = -1e30f, l0 = 0.0f, l1 = 0.0f;
    const float LOG2E = 1.4426950408889634f;
    const float SCL   = 0.125f;   // 1/sqrt(64)

    int st = 0;
    for (int kt = 0; kt < SEQ / 64; kt++, st ^= 1) {
        if (kt + 1 < SEQ / 64) { load_kv(st ^ 1, kt + 1); CP_WAIT1(); }
        else                   { CP_WAIT0(); }
        __syncthreads();

        const float* cK = sm + QT + st * ST;
        const float* cV = sm + QT + 2 * ST + st * ST;

        // S = Q @ K^T   (this warp: its 16 rows x all 64 cols)
        float sc[8][4] = {};
        #pragma unroll
        for (int kk = 0; kk < 8; kk++) {
            #pragma unroll
            for (int ni = 0; ni < 8; ni++) {
                uint32_t bb[2];
                int rn = ni * 8 + g;
                bb[0] = __float_as_uint(cK[rn * 68 + kk * 8 + t]);
                bb[1] = __float_as_uint(cK[rn * 68 + kk * 8 + t + 4]);
                mma_tf32(sc[ni], qa[kk], bb);
            }
        }

        // online softmax (rows pr, pr+8)
        #pragma unroll
        for (int ni = 0; ni < 8; ni++)
            #pragma unroll
            for (int j = 0; j < 4; j++) sc[ni][j] *= SCL;

        float mx0 = -1e30f, mx1 = -1e30f;
        #pragma unroll
        for (int ni = 0; ni < 8; ni++) {
            mx0 = fmaxf(mx0, fmaxf(sc[ni][0], sc[ni][1]));
            mx1 = fmaxf(mx1, fmaxf(sc[ni][2], sc[ni][3]));
        }
        mx0 = fmaxf(mx0, __shfl_xor_sync(0xffffffffu, mx0, 1));
        mx0 = fmaxf(mx0, __shfl_xor_sync(0xffffffffu, mx0, 2));
        mx1 = fmaxf(mx1, __shfl_xor_sync(0xffffffffu, mx1, 1));
        mx1 = fmaxf(mx1, __shfl_xor_sync(0xffffffffu, mx1, 2));

        float mn0 = fmaxf(m0, mx0);
        float mn1 = fmaxf(m1, mx1);
        float a0 = exp2f((m0 - mn0) * LOG2E);
        float a1 = exp2f((m1 - mn1) * LOG2E);
        m0 = mn0; m1 = mn1;

        float rs0 = 0.0f, rs1 = 0.0f;
        #pragma unroll
        for (int ni = 0; ni < 8; ni++) {
            sc[ni][0] = exp2f((sc[ni][0] - m0) * LOG2E);
            sc[ni][1] = exp2f((sc[ni][1] - m0) * LOG2E);
            sc[ni][2] = exp2f((sc[ni][2] - m1) * LOG2E);
            sc[ni][3] = exp2f((sc[ni][3] - m1) * LOG2E);
            rs0 += sc[ni][0] + sc[ni][1];
            rs1 += sc[ni][2] + sc[ni][3];
        }
        rs0 += __shfl_xor_sync(0xffffffffu, rs0, 1);
        rs0 += __shfl_xor_sync(0xffffffffu, rs0, 2);
        rs1 += __shfl_xor_sync(0xffffffffu, rs1, 1);
        rs1 += __shfl_xor_sync(0xffffffffu, rs1, 2);
        l0 = l0 * a0 + rs0;
        l1 = l1 * a1 + rs1;

        #pragma unroll
        for (int ni = 0; ni < 8; ni++) {
            oc[ni][0] *= a0; oc[ni][1] *= a0;
            oc[ni][2] *= a1; oc[ni][3] *= a1;
        }

        // store P as tf32 (warp-private rows of sQ region)
        #pragma unroll
        for (int ni = 0; ni < 8; ni++) {
            int cc = ni * 8 + 2 * t;
            sQ[pr * 68 + cc]           = __uint_as_float(f2tf(sc[ni][0]));
            sQ[pr * 68 + cc + 1]       = __uint_as_float(f2tf(sc[ni][1]));
            sQ[(pr + 8) * 68 + cc]     = __uint_as_float(f2tf(sc[ni][2]));
            sQ[(pr + 8) * 68 + cc + 1] = __uint_as_float(f2tf(sc[ni][3]));
        }
        __syncwarp();

        // O += P @ V   (V transposed: cV[d][kpos])
        #pragma unroll
        for (int kk = 0; kk < 8; kk++) {
            uint32_t pa[4];
            pa[0] = __float_as_uint(sQ[pr * 68 + kk * 8 + t]);
            pa[1] = __float_as_uint(sQ[(pr + 8) * 68 + kk * 8 + t]);
            pa[2] = __float_as_uint(sQ[pr * 68 + kk * 8 + t + 4]);
            pa[3] = __float_as_uint(sQ[(pr + 8) * 68 + kk * 8 + t + 4]);
            #pragma unroll
            for (int ni = 0; ni < 8; ni++) {
                uint32_t bb[2];
                int rn = ni * 8 + g;
                bb[0] = __float_as_uint(cV[rn * 68 + kk * 8 + t]);
                bb[1] = __float_as_uint(cV[rn * 68 + kk * 8 + t + 4]);
                mma_tf32(oc[ni], pa, bb);
            }
        }
        __syncthreads();
    }

    // epilogue: normalize, write g_att (tf32) as [B, S, H*hd]
    float i0 = 1.0f / l0;
    float i1 = 1.0f / l1;
    int r0 = qt * 128 + warp * 16 + g;
    float* Og = g_att + (size_t)b * SEQ * EDIM + (size_t)h * HDIM;
    #pragma unroll
    for (int ni = 0; ni < 8; ni++) {
        int cc = ni * 8 + 2 * t;
        Og[(size_t)r0 * EDIM + cc]           = __uint_as_float(f2tf(oc[ni][0] * i0));
        Og[(size_t)r0 * EDIM + cc + 1]       = __uint_as_float(f2tf(oc[ni][1] * i0));
        Og[(size_t)(r0 + 8) * EDIM + cc]     = __uint_as_float(f2tf(oc[ni][2] * i1));
        Og[(size_t)(r0 + 8) * EDIM + cc + 1] = __uint_as_float(f2tf(oc[ni][3] * i1));
    }
}

extern "C" void kernel_launch(void* const* d_in, const int* in_sizes, int n_in,
                              void* d_out, int out_size)
{
    const float* x     = (const float*)d_in[0];
    const float* hmask = (const float*)d_in[1];
    const float* qkv_w = (const float*)d_in[2];
    const float* qkv_b = (const float*)d_in[3];
    const float* fc_w  = (const float*)d_in[4];
    const float* fc_b  = (const float*)d_in[5];
    float* out = (float*)d_out;

    const int gemm_smem = 3 * 2 * 128 * 36 * (int)sizeof(float);         // 110592
    const int fa_smem   = (128 * 68 + 4 * 64 * 68) * (int)sizeof(float); // 104448

    cudaFuncSetAttribute(gemm_tf32_kernel<1>,
                         cudaFuncAttributeMaxDynamicSharedMemorySize, gemm_smem);
    cudaFuncSetAttribute(gemm_tf32_kernel<0>,
                         cudaFuncAttributeMaxDynamicSharedMemorySize, gemm_smem);
    cudaFuncSetAttribute(flash_attn_kernel,
                         cudaFuncAttributeMaxDynamicSharedMemorySize, fa_smem);

    float* xc   = nullptr; cudaGetSymbolAddress((void**)&xc,   g_xc);
    float* wqkv = nullptr; cudaGetSymbolAddress((void**)&wqkv, g_wqkv);
    float* wfc  = nullptr; cudaGetSymbolAddress((void**)&wfc,  g_wfc);

    // 0) pre-convert operands to tf32 (memory-bound, cheap)
    cvt_tf32_kernel<<<(BATCH * SEQ * EDIM / 4 + 255) / 256, 256>>>(x, xc, BATCH * SEQ * EDIM / 4);
    cvt_tf32_kernel<<<(3 * EDIM * EDIM / 4 + 255) / 256, 256>>>(qkv_w, wqkv, 3 * EDIM * EDIM / 4);
    cvt_tf32_kernel<<<(EDIM * EDIM / 4 + 255) / 256, 256>>>(fc_w, wfc, EDIM * EDIM / 4);

    // 1) QKV projection + bias + head_mask + scatter (q/k tf32, v tf32 transposed)
    gemm_tf32_kernel<1><<<dim3(3 * EDIM / 128, BATCH * SEQ / 128), 256, gemm_smem>>>(
        qkv_b, hmask, nullptr, BATCH * SEQ, 3 * EDIM, EDIM);

    // 2) flash attention -> g_att [B,S,D] (tf32)
    flash_attn_kernel<<<dim3(SEQ / 128, NHEAD, BATCH), 256, fa_smem>>>();

    // 3) output projection + bias -> d_out (fp32)
    gemm_tf32_kernel<0><<<dim3(EDIM / 128, BATCH * SEQ / 128), 256, gemm_smem>>>(
        fc_b, nullptr, out, BATCH * SEQ, EDIM, EDIM);
}

// round 6
// speedup vs baseline: 1.3414x; 1.0166x over previous
#include <cuda_runtime.h>
#include <cstdint>

#define BATCH 2
#define SEQ   2048
#define NHEAD 16
#define HDIM  64
#define EDIM  1024

// Scratch (static device globals: allocation-free per harness rules)
__device__ float g_q[(size_t)BATCH * NHEAD * SEQ * HDIM];     // tf32
__device__ float g_k[(size_t)BATCH * NHEAD * SEQ * HDIM];     // tf32
__device__ float g_v[(size_t)BATCH * NHEAD * SEQ * HDIM];     // tf32, TRANSPOSED [b,h,d,s]
__device__ float g_att[(size_t)BATCH * SEQ * EDIM];           // tf32
__device__ float g_xc[(size_t)BATCH * SEQ * EDIM];            // x as tf32
__device__ float g_wqkv[(size_t)3 * EDIM * EDIM];             // qkv_w as tf32
__device__ float g_wfc[(size_t)EDIM * EDIM];                  // fc_w as tf32

__device__ __forceinline__ uint32_t f2tf(float f) {
    uint32_t u;
    asm("cvt.rna.tf32.f32 %0, %1;" : "=r"(u) : "f"(f));
    return u;
}

__device__ __forceinline__ uint32_t smem_u32(const void* p) {
    return (uint32_t)__cvta_generic_to_shared(p);
}

#define CP_A16(dst, src) \
    asm volatile("cp.async.cg.shared.global [%0], [%1], 16;" :: "r"(dst), "l"(src) : "memory")
#define CP_COMMIT() asm volatile("cp.async.commit_group;" ::: "memory")
#define CP_WAIT0()  asm volatile("cp.async.wait_group 0;" ::: "memory")
#define CP_WAIT1()  asm volatile("cp.async.wait_group 1;" ::: "memory")

__device__ __forceinline__ void mma_tf32(float* c, const uint32_t* a, const uint32_t* b) {
    asm volatile(
        "mma.sync.aligned.m16n8k8.row.col.f32.tf32.tf32.f32 "
        "{%0,%1,%2,%3}, {%4,%5,%6,%7}, {%8,%9}, {%0,%1,%2,%3};"
        : "+f"(c[0]), "+f"(c[1]), "+f"(c[2]), "+f"(c[3])
        : "r"(a[0]), "r"(a[1]), "r"(a[2]), "r"(a[3]), "r"(b[0]), "r"(b[1]));
}

// ldmatrix x4: 4 8x4(tf32) blocks. Lane groups 0-7/8-15/16-23/24-31 supply row
// addresses of matrices 0..3; reg rK = fragment of matrix K (lane i -> row i/4, col i%4).
__device__ __forceinline__ void ldsm_x4(uint32_t& r0, uint32_t& r1,
                                        uint32_t& r2, uint32_t& r3, uint32_t addr) {
    asm volatile("ldmatrix.sync.aligned.m8n8.x4.shared.b16 {%0,%1,%2,%3}, [%4];"
                 : "=r"(r0), "=r"(r1), "=r"(r2), "=r"(r3) : "r"(addr));
}

// ---------------------------------------------------------------------------
// Elementwise fp32 -> tf32 conversion (memory-bound, cheap)
// ---------------------------------------------------------------------------
__global__ void cvt_tf32_kernel(const float* __restrict__ in,
                                float* __restrict__ out, int n4)
{
    int i = blockIdx.x * blockDim.x + threadIdx.x;
    if (i >= n4) return;
    float4 v = ((const float4*)in)[i];
    uint4 o;
    o.x = f2tf(v.x); o.y = f2tf(v.y); o.z = f2tf(v.z); o.w = f2tf(v.w);
    ((uint4*)out)[i] = o;
}

// Scatter one QKV output element with bias + head_mask, stored as tf32.
// V goes TRANSPOSED [b,h,d,s].
__device__ __forceinline__ void store_qkv_elem(int r, int e, float v,
                                               const float* bias, const float* mask) {
    int bb  = r >> 11;            // batch (S=2048)
    int s   = r & (SEQ - 1);
    int h   = e / 192;            // 3*hd = 192 per head
    int rem = e - h * 192;
    int which = rem >> 6;         // 0=q, 1=k, 2=v
    int j   = rem & 63;
    float val = __uint_as_float(f2tf((v + bias[e]) * mask[h]));
    size_t bh = (size_t)(bb * NHEAD + h);
    if (which == 0)      g_q[(bh * SEQ + s) * HDIM + j] = val;
    else if (which == 1) g_k[(bh * SEQ + s) * HDIM + j] = val;
    else                 g_v[(bh * HDIM + j) * SEQ + s] = val;
}

// ---------------------------------------------------------------------------
// tf32 GEMM: C[M,N] = A[M,K] @ W[N,K]^T. Inputs already tf32 in gmem.
// 3-stage cp.async pipeline, one __syncthreads per K-step, LDSM frag loads.
// BM=BN=128, BK=32; 256 thr (4x2 warps, 32x64 warp tile); stride 36 (CF).
// ---------------------------------------------------------------------------
template <int MODE>
__global__ __launch_bounds__(256, 2)
void gemm_tf32_kernel(const float* __restrict__ bias,
                      const float* __restrict__ mask,
                      float* __restrict__ out,
                      int M, int N, int K)
{
    extern __shared__ float smp[];
    const int SA = 128 * 36;               // one operand tile (words)
    const uint32_t smu = smem_u32(smp);

    const int tid  = threadIdx.x;
    const int warp = tid >> 5;
    const int lane = tid & 31;
    const int g    = lane >> 2;
    const int t    = lane & 3;
    const int wm   = warp >> 1;
    const int wn   = warp & 1;
    const int m0   = blockIdx.y * 128;
    const int n0   = blockIdx.x * 128;

    // ldmatrix per-lane row-address pattern (words), stride 36
    const uint32_t offpat = (uint32_t)(((lane & 8) + (lane & 7)) * 36 + ((lane >> 4) << 2));

    const float* Ap = (MODE == 0) ? (const float*)g_att : (const float*)g_xc;
    const float* Wp = (MODE == 0) ? (const float*)g_wfc : (const float*)g_wqkv;

    const int lrow = tid >> 3;        // 0..31
    const int lcol = (tid & 7) << 2;  // 0,4,...,28

    const float* agp = Ap + (size_t)(m0 + lrow) * K + lcol;
    const float* bgp = Wp + (size_t)(n0 + lrow) * K + lcol;

    auto gissue = [&](int st, int k0) {
        #pragma unroll
        for (int i = 0; i < 4; i++) {
            uint32_t offA = (uint32_t)((st * 2 * SA + (lrow + i * 32) * 36 + lcol) << 2);
            CP_A16(smu + offA,             agp + (size_t)i * 32 * K + k0);
            CP_A16(smu + offA + (SA << 2), bgp + (size_t)i * 32 * K + k0);
        }
        CP_COMMIT();
    };

    float acc[2][8][4] = {};

    const int NK = K / 32;
    gissue(0, 0);
    gissue(1, 32);

    for (int ki = 0; ki < NK; ki++) {
        if (ki + 2 < NK) { CP_WAIT1(); }
        else             { CP_WAIT0(); }
        __syncthreads();
        if (ki + 2 < NK) gissue((ki + 2) % 3, (ki + 2) * 32);

        const uint32_t stA = smu + (((ki % 3) * 2 * SA + wm * 32 * 36 + offpat) << 2);
        const uint32_t stB = smu + (((ki % 3) * 2 * SA + SA + wn * 64 * 36 + offpat) << 2);

        #pragma unroll
        for (int kk = 0; kk < 4; kk++) {
            uint32_t a[2][4];
            uint32_t bb[8][2];
            ldsm_x4(a[0][0], a[0][1], a[0][2], a[0][3], stA + (kk * 8 << 2));
            ldsm_x4(a[1][0], a[1][1], a[1][2], a[1][3], stA + ((16 * 36 + kk * 8) << 2));
            #pragma unroll
            for (int nb = 0; nb < 4; nb++)
                ldsm_x4(bb[2 * nb][0], bb[2 * nb + 1][0], bb[2 * nb][1], bb[2 * nb + 1][1],
                        stB + ((nb * 16 * 36 + kk * 8) << 2));
            #pragma unroll
            for (int mi = 0; mi < 2; mi++)
                #pragma unroll
                for (int ni = 0; ni < 8; ni++)
                    mma_tf32(acc[mi][ni], a[mi], bb[ni]);
        }
    }

    // Epilogue
    #pragma unroll
    for (int mi = 0; mi < 2; mi++) {
        #pragma unroll
        for (int ni = 0; ni < 8; ni++) {
            int r0 = m0 + wm * 32 + mi * 16 + g;
            int cc = n0 + wn * 64 + ni * 8 + 2 * t;
            if (MODE == 0) {
                float b0 = bias[cc], b1 = bias[cc + 1];
                out[(size_t)r0 * N + cc]           = acc[mi][ni][0] + b0;
                out[(size_t)r0 * N + cc + 1]       = acc[mi][ni][1] + b1;
                out[(size_t)(r0 + 8) * N + cc]     = acc[mi][ni][2] + b0;
                out[(size_t)(r0 + 8) * N + cc + 1] = acc[mi][ni][3] + b1;
            } else {
                store_qkv_elem(r0,     cc,     acc[mi][ni][0], bias, mask);
                store_qkv_elem(r0,     cc + 1, acc[mi][ni][1], bias, mask);
                store_qkv_elem(r0 + 8, cc,     acc[mi][ni][2], bias, mask);
                store_qkv_elem(r0 + 8, cc + 1, acc[mi][ni][3], bias, mask);
            }
        }
    }
}

// ---------------------------------------------------------------------------
// Flash attention: CTA = (b, h, 128-row q-tile), 256 thr (8 warps x 16 rows).
// LDSM fragment loads; cp.async double-buffered K/V; V pre-transposed.
// smem stride 68 (==4 mod 32 words -> conflict-free LDSM phases).
// ---------------------------------------------------------------------------
__global__ __launch_bounds__(256, 2)
void flash_attn_kernel()
{
    extern __shared__ float sm[];
    const int QT = 128 * 68;      // Q region (reused as P), words
    const int ST = 64 * 68;       // one K or V stage, words
    float* sQ = sm;
    const uint32_t smu = smem_u32(sm);

    const int tid  = threadIdx.x;
    const int warp = tid >> 5;
    const int lane = tid & 31;
    const int g    = lane >> 2;
    const int t    = lane & 3;
    const int qt = blockIdx.x;
    const int h  = blockIdx.y;
    const int b  = blockIdx.z;

    const uint32_t offpat68 = (uint32_t)(((lane & 8) + (lane & 7)) * 68 + ((lane >> 4) << 2));

    const size_t baseQK = ((size_t)(b * NHEAD + h)) * SEQ * HDIM;
    const float* Qg = g_q + baseQK + (size_t)qt * 128 * HDIM;
    const float* Kg = g_k + baseQK;
    const float* Vg = g_v + ((size_t)(b * NHEAD + h)) * HDIM * SEQ;   // [d][s]

    // --- async load Q tile (128x64) ---
    #pragma unroll
    for (int i = 0; i < 8; i++) {
        int id = tid + i * 256;
        int r  = id >> 4;
        int c  = (id & 15) << 2;
        CP_A16(smu + ((r * 68 + c) << 2), Qg + r * HDIM + c);
    }
    CP_COMMIT();

    auto load_kv = [&](int st, int kt) {
        #pragma unroll
        for (int i = 0; i < 4; i++) {
            int id = tid + i * 256;
            int r  = id >> 4;
            int c  = (id & 15) << 2;
            CP_A16(smu + ((QT + st * ST + r * 68 + c) << 2),
                   Kg + ((size_t)kt * 64 + r) * HDIM + c);
            CP_A16(smu + ((QT + 2 * ST + st * ST + r * 68 + c) << 2),
                   Vg + (size_t)r * SEQ + kt * 64 + c);
        }
        CP_COMMIT();
    };

    load_kv(0, 0);
    CP_WAIT1();       // Q group done (KV0 may still be in flight)
    __syncthreads();

    // Extract Q A-fragments via LDSM; sQ region then becomes P.
    uint32_t qa[8][4];
    const int pr = warp * 16 + g;
    const uint32_t qBase = smu + ((warp * 16 * 68 + offpat68) << 2);
    #pragma unroll
    for (int kk = 0; kk < 8; kk++)
        ldsm_x4(qa[kk][0], qa[kk][1], qa[kk][2], qa[kk][3], qBase + (kk * 8 << 2));
    __syncthreads();   // everyone has Q frags before sQ is reused as P

    float oc[8][4] = {};
    float m0 = -1e30f, m1 = -1e30f, l0 = 0.0f, l1 = 0.0f;
    const float LOG2E = 1.4426950408889634f;
    const float SCL   = 0.125f;   // 1/sqrt(64)

    int st = 0;
    for (int kt = 0; kt < SEQ / 64; kt++, st ^= 1) {
        if (kt + 1 < SEQ / 64) { load_kv(st ^ 1, kt + 1); CP_WAIT1(); }
        else                   { CP_WAIT0(); }
        __syncthreads();

        const uint32_t kBase = smu + ((QT + st * ST + offpat68) << 2);
        const uint32_t vBase = smu + ((QT + 2 * ST + st * ST + offpat68) << 2);

        // S = Q @ K^T
        float sc[8][4] = {};
        #pragma unroll
        for (int kk = 0; kk < 8; kk++) {
            uint32_t bb[8][2];
            #pragma unroll
            for (int nb = 0; nb < 4; nb++)
                ldsm_x4(bb[2 * nb][0], bb[2 * nb + 1][0], bb[2 * nb][1], bb[2 * nb + 1][1],
                        kBase + ((nb * 16 * 68 + kk * 8) << 2));
            #pragma unroll
            for (int ni = 0; ni < 8; ni++)
                mma_tf32(sc[ni], qa[kk], bb[ni]);
        }

        // online softmax (rows pr, pr+8)
        #pragma unroll
        for (int ni = 0; ni < 8; ni++)
            #pragma unroll
            for (int j = 0; j < 4; j++) sc[ni][j] *= SCL;

        float mx0 = -1e30f, mx1 = -1e30f;
        #pragma unroll
        for (int ni = 0; ni < 8; ni++) {
            mx0 = fmaxf(mx0, fmaxf(sc[ni][0], sc[ni][1]));
            mx1 = fmaxf(mx1, fmaxf(sc[ni][2], sc[ni][3]));
        }
        mx0 = fmaxf(mx0, __shfl_xor_sync(0xffffffffu, mx0, 1));
        mx0 = fmaxf(mx0, __shfl_xor_sync(0xffffffffu, mx0, 2));
        mx1 = fmaxf(mx1, __shfl_xor_sync(0xffffffffu, mx1, 1));
        mx1 = fmaxf(mx1, __shfl_xor_sync(0xffffffffu, mx1, 2));

        float mn0 = fmaxf(m0, mx0);
        float mn1 = fmaxf(m1, mx1);
        float a0 = exp2f((m0 - mn0) * LOG2E);
        float a1 = exp2f((m1 - mn1) * LOG2E);
        m0 = mn0; m1 = mn1;

        float rs0 = 0.0f, rs1 = 0.0f;
        #pragma unroll
        for (int ni = 0; ni < 8; ni++) {
            sc[ni][0] = exp2f((sc[ni][0] - m0) * LOG2E);
            sc[ni][1] = exp2f((sc[ni][1] - m0) * LOG2E);
            sc[ni][2] = exp2f((sc[ni][2] - m1) * LOG2E);
            sc[ni][3] = exp2f((sc[ni][3] - m1) * LOG2E);
            rs0 += sc[ni][0] + sc[ni][1];
            rs1 += sc[ni][2] + sc[ni][3];
        }
        rs0 += __shfl_xor_sync(0xffffffffu, rs0, 1);
        rs0 += __shfl_xor_sync(0xffffffffu, rs0, 2);
        rs1 += __shfl_xor_sync(0xffffffffu, rs1, 1);
        rs1 += __shfl_xor_sync(0xffffffffu, rs1, 2);
        l0 = l0 * a0 + rs0;
        l1 = l1 * a1 + rs1;

        #pragma unroll
        for (int ni = 0; ni < 8; ni++) {
            oc[ni][0] *= a0; oc[ni][1] *= a0;
            oc[ni][2] *= a1; oc[ni][3] *= a1;
        }

        // store P as tf32 (warp-private rows of sQ region)
        #pragma unroll
        for (int ni = 0; ni < 8; ni++) {
            int cc = ni * 8 + 2 * t;
            sQ[pr * 68 + cc]           = __uint_as_float(f2tf(sc[ni][0]));
            sQ[pr * 68 + cc + 1]       = __uint_as_float(f2tf(sc[ni][1]));
            sQ[(pr + 8) * 68 + cc]     = __uint_as_float(f2tf(sc[ni][2]));
            sQ[(pr + 8) * 68 + cc + 1] = __uint_as_float(f2tf(sc[ni][3]));
        }
        __syncwarp();

        // O += P @ V   (V transposed: cV[d][kpos])
        #pragma unroll
        for (int kk = 0; kk < 8; kk++) {
            uint32_t pa[4];
            ldsm_x4(pa[0], pa[1], pa[2], pa[3], qBase + (kk * 8 << 2));
            uint32_t bb[8][2];
            #pragma unroll
            for (int nb = 0; nb < 4; nb++)
                ldsm_x4(bb[2 * nb][0], bb[2 * nb + 1][0], bb[2 * nb][1], bb[2 * nb + 1][1],
                        vBase + ((nb * 16 * 68 + kk * 8) << 2));
            #pragma unroll
            for (int ni = 0; ni < 8; ni++)
                mma_tf32(oc[ni], pa, bb[ni]);
        }
        __syncthreads();
    }

    // epilogue: normalize, write g_att (tf32) as [B, S, H*hd]
    float i0 = 1.0f / l0;
    float i1 = 1.0f / l1;
    int r0 = qt * 128 + warp * 16 + g;
    float* Og = g_att + (size_t)b * SEQ * EDIM + (size_t)h * HDIM;
    #pragma unroll
    for (int ni = 0; ni < 8; ni++) {
        int cc = ni * 8 + 2 * t;
        Og[(size_t)r0 * EDIM + cc]           = __uint_as_float(f2tf(oc[ni][0] * i0));
        Og[(size_t)r0 * EDIM + cc + 1]       = __uint_as_float(f2tf(oc[ni][1] * i0));
        Og[(size_t)(r0 + 8) * EDIM + cc]     = __uint_as_float(f2tf(oc[ni][2] * i1));
        Og[(size_t)(r0 + 8) * EDIM + cc + 1] = __uint_as_float(f2tf(oc[ni][3] * i1));
    }
}

extern "C" void kernel_launch(void* const* d_in, const int* in_sizes, int n_in,
                              void* d_out, int out_size)
{
    const float* x     = (const float*)d_in[0];
    const float* hmask = (const float*)d_in[1];
    const float* qkv_w = (const float*)d_in[2];
    const float* qkv_b = (const float*)d_in[3];
    const float* fc_w  = (const float*)d_in[4];
    const float* fc_b  = (const float*)d_in[5];
    float* out = (float*)d_out;

    const int gemm_smem = 3 * 2 * 128 * 36 * (int)sizeof(float);         // 110592
    const int fa_smem   = (128 * 68 + 4 * 64 * 68) * (int)sizeof(float); // 104448

    cudaFuncSetAttribute(gemm_tf32_kernel<1>,
                         cudaFuncAttributeMaxDynamicSharedMemorySize, gemm_smem);
    cudaFuncSetAttribute(gemm_tf32_kernel<0>,
                         cudaFuncAttributeMaxDynamicSharedMemorySize, gemm_smem);
    cudaFuncSetAttribute(flash_attn_kernel,
                         cudaFuncAttributeMaxDynamicSharedMemorySize, fa_smem);

    float* xc   = nullptr; cudaGetSymbolAddress((void**)&xc,   g_xc);
    float* wqkv = nullptr; cudaGetSymbolAddress((void**)&wqkv, g_wqkv);
    float* wfc  = nullptr; cudaGetSymbolAddress((void**)&wfc,  g_wfc);

    // 0) pre-convert operands to tf32 (memory-bound, cheap)
    cvt_tf32_kernel<<<(BATCH * SEQ * EDIM / 4 + 255) / 256, 256>>>(x, xc, BATCH * SEQ * EDIM / 4);
    cvt_tf32_kernel<<<(3 * EDIM * EDIM / 4 + 255) / 256, 256>>>(qkv_w, wqkv, 3 * EDIM * EDIM / 4);
    cvt_tf32_kernel<<<(EDIM * EDIM / 4 + 255) / 256, 256>>>(fc_w, wfc, EDIM * EDIM / 4);

    // 1) QKV projection + bias + head_mask + scatter (q/k tf32, v tf32 transposed)
    gemm_tf32_kernel<1><<<dim3(3 * EDIM / 128, BATCH * SEQ / 128), 256, gemm_smem>>>(
        qkv_b, hmask, nullptr, BATCH * SEQ, 3 * EDIM, EDIM);

    // 2) flash attention -> g_att [B,S,D] (tf32)
    flash_attn_kernel<<<dim3(SEQ / 128, NHEAD, BATCH), 256, fa_smem>>>();

    // 3) output projection + bias -> d_out (fp32)
    gemm_tf32_kernel<0><<<dim3(EDIM / 128, BATCH * SEQ / 128), 256, gemm_smem>>>(
        fc_b, nullptr, out, BATCH * SEQ, EDIM, EDIM);
}